// round 13
// baseline (speedup 1.0000x reference)
#include <cuda_runtime.h>
#include <math.h>

#define NB 16
#define NT 60
#define NCLS 80

__constant__ float cANW[9] = {12.f,19.f,40.f,36.f,76.f,72.f,142.f,192.f,459.f};
__constant__ float cANH[9] = {16.f,36.f,28.f,75.f,55.f,146.f,110.f,243.f,401.f};
// atan(w/h) per anchor — scale-invariant constants (<5e-6 abs err; argmax gaps O(1e-2))
__constant__ float cATAN[9] = {0.6435011f, 0.4856221f, 0.9600704f,
                               0.4475200f, 0.9443511f, 0.4581533f,
                               0.9117062f, 0.6686896f, 0.8527381f};

#define FSQ0 5776
#define FSQ1 1444
#define FSQ2 361

#define TPB 512                      /* 16 warps/block: doubles resident warps at same grid */
#define CELLS 1024                   /* cells per main block (CPT=2 now) */
#define CH0 17
#define CH1 5
#define CH2 2
#define MATCHB 16                    /* one match block per batch b */
#define MAINB (NB*(CH0+CH1+CH2))     /* 384 */
#define GRID (MATCHB + MAINB)        /* 400 */

__device__ float g_partial[GRID][5]; // fully rewritten each run — replay safe
__device__ int   g_done;             // reset to 0 by last block each run

__device__ __forceinline__ float clogf_(float v){ return fmaxf(__logf(v), -100.0f); }
__device__ __forceinline__ float sigf_(float v){ return __fdividef(1.0f, 1.0f + __expf(-v)); }

// CIoU argmax over 9 anchors at L0 scale (scale-invariant across levels)
__device__ __forceinline__ int ciou_argmax(float tw, float th){
  float at_t = atanf(tw/th);
  float twth = tw*th;
  float best = -3.0e38f; int bi = 0;
  #pragma unroll
  for (int k = 0; k < 9; k++){
    float wb = cANW[k]*0.125f, hb = cANH[k]*0.125f;
    float ai = fminf(tw,wb)*fminf(th,hb);
    float au = twth + wb*hb - ai;
    float iou = ai/au;
    float mw = fmaxf(tw,wb), mh = fmaxf(th,hb);
    float c2 = mw*mw + mh*mh + 1e-16f;
    float dw = tw-wb, dh = th-hb;
    float rho2 = (dw*dw + dh*dh)*0.25f;
    float da = at_t - cATAN[k];
    float v = 0.40528473455296503f*(da*da);      // 4/pi^2
    float alpha = v/(1.0f - iou + v);
    float ciou = iou - (rho2/c2 + v*alpha);
    if (ciou > best){ best = ciou; bi = k; }     // first-max == jnp.argmax
  }
  return bi;
}

// ------------------------------------------------------------------ main-path context (corner form, 2 cells/thread)
template<int L, int FS>
struct Ctx {
  float so[2], plx[2], ply[2], phx[2], phy[2], ap3[2];
  int base;
};

template<int L, int FS>
__device__ __forceinline__ void main_pre(const float* __restrict__ x, int b, int chunk, Ctx<L,FS>& c){
  constexpr int FSQ = FS*FS;
  constexpr float invs = (L==0) ? 0.125f : 0.0625f;
  c.base = chunk*CELLS + (int)threadIdx.x*2;
  #pragma unroll
  for (int k = 0; k < 2; k++){
    c.so[k] = 0.f; c.plx[k] = 3e4f; c.phx[k] = 3e4f; c.ply[k] = 0.f; c.phy[k] = 0.f; c.ap3[k] = 1.f;
  }
  if (c.base < 3*FSQ){
    int a = c.base/FSQ, cell = c.base - a*FSQ;    // FSQ,FS even => pair stays in plane/row
    int j0 = cell / FS, i0 = cell - j0*FS;
    const float* xp = x + (b*255 + a*85)*FSQ + cell;
    float2 O0 = __ldg((const float2*)(xp));
    float2 O1 = __ldg((const float2*)(xp+FSQ));
    float2 O2 = __ldg((const float2*)(xp+2*FSQ));
    float2 O3 = __ldg((const float2*)(xp+3*FSQ));
    float2 O4 = __ldg((const float2*)(xp+4*FSQ));
    float AW = cANW[3*L+a]*invs, AH = cANH[3*L+a]*invs;
    float o0a[2] = {O0.x,O0.y};
    float o1a[2] = {O1.x,O1.y};
    float o2a[2] = {O2.x,O2.y};
    float o3a[2] = {O3.x,O3.y};
    float o4a[2] = {O4.x,O4.y};
    float fj = (float)j0;
    #pragma unroll
    for (int k = 0; k < 2; k++){
      c.so[k] = sigf_(o4a[k]);
      float pw = __expf(o2a[k])*AW, ph = __expf(o3a[k])*AH;
      float px = (float)(i0+k) + sigf_(o0a[k]);
      float py = fj + sigf_(o1a[k]);
      float hw = 0.5f*pw, hh = 0.5f*ph;
      c.plx[k] = px-hw; c.phx[k] = px+hw; c.ply[k] = py-hh; c.phy[k] = py+hh;
      c.ap3[k] = pw*ph*(1.0f/3.0f);
    }
  }
}

template<int L, int FS>
__device__ __forceinline__ void main_post(const Ctx<L,FS>& c, int nv, int hm,
    const float4* s_box, const float* s_ar3, const unsigned char* s_mbit, float* acc){
  constexpr int FSQ = FS*FS;
  bool un[2] = {false,false};
  if (c.base < 3*FSQ){
    uchar2 mb = *(const uchar2*)(s_mbit + threadIdx.x*2);
    unsigned char m[2] = {mb.x, mb.y};
    #pragma unroll
    for (int k = 0; k < 2; k++){
      if (m[k]){ acc[2] += -clogf_(c.so[k]); float e = c.so[k]-1.f; acc[4] += e*e; }
      else un[k] = true;
    }
  }
  float vmax[2] = {-1e30f,-1e30f};
  if (hm){
    #pragma unroll 4
    for (int t = 0; t < nv; t++){
      float4 tb = s_box[t];
      float ar3 = s_ar3[t];
      #pragma unroll
      for (int k = 0; k < 2; k++){
        float wi = fmaxf(fminf(c.phx[k], tb.z) - fmaxf(c.plx[k], tb.x), 0.f);
        float hi = fminf(c.phy[k], tb.w) - fmaxf(c.ply[k], tb.y);
        vmax[k] = fmaxf(vmax[k], fmaf(wi, hi, -ar3));     // iou>.5 <=> ai-at/3 > ap/3
      }
    }
  }
  #pragma unroll
  for (int k = 0; k < 2; k++){
    if (un[k] && !(vmax[k] > c.ap3[k])){ acc[2] += -clogf_(1.f - c.so[k]); acc[4] += c.so[k]*c.so[k]; }
  }
}

// scalar variant for L2 (FSQ=361, odd)
struct Ctx2 {
  float so[2], plx[2], ply[2], phx[2], phy[2], ap3[2];
  int base;
};

__device__ __forceinline__ void main_pre2(const float* __restrict__ x, int b, int chunk, Ctx2& c){
  constexpr int FSQ = FSQ2;
  constexpr float invs = 0.03125f;
  c.base = chunk*CELLS + (int)threadIdx.x;
  #pragma unroll
  for (int k = 0; k < 2; k++){
    int cc = c.base + k*TPB;
    c.so[k] = 0.f; c.plx[k] = 3e4f; c.phx[k] = 3e4f; c.ply[k] = 0.f; c.phy[k] = 0.f; c.ap3[k] = 1.f;
    if (cc < 3*FSQ){
      int a = cc/FSQ, cell = cc - a*FSQ;
      const float* xp = x + (b*255 + a*85)*FSQ + cell;
      c.so[k] = sigf_(__ldg(xp + 4*FSQ));
      float AW = cANW[6+a]*invs, AH = cANH[6+a]*invs;
      float pw = __expf(__ldg(xp+2*FSQ))*AW, ph = __expf(__ldg(xp+3*FSQ))*AH;
      float px = (float)(cell % 19) + sigf_(__ldg(xp));
      float py = (float)(cell / 19) + sigf_(__ldg(xp+FSQ));
      float hw = 0.5f*pw, hh = 0.5f*ph;
      c.plx[k] = px-hw; c.phx[k] = px+hw; c.ply[k] = py-hh; c.phy[k] = py+hh;
      c.ap3[k] = pw*ph*(1.0f/3.0f);
    }
  }
}

__device__ __forceinline__ void main_post2(const Ctx2& c, int nv, int hm,
    const float4* s_box, const float* s_ar3, const unsigned char* s_mbit, float* acc){
  constexpr int FSQ = FSQ2;
  bool un[2] = {false,false};
  #pragma unroll
  for (int k = 0; k < 2; k++){
    int cc = c.base + k*TPB;
    if (cc < 3*FSQ){
      if (s_mbit[(int)threadIdx.x + k*TPB]){ acc[2] += -clogf_(c.so[k]); float e = c.so[k]-1.f; acc[4] += e*e; }
      else un[k] = true;
    }
  }
  float vmax[2] = {-1e30f,-1e30f};
  if (hm){
    for (int t = 0; t < nv; t++){
      float4 tb = s_box[t];
      float ar3 = s_ar3[t];
      #pragma unroll
      for (int k = 0; k < 2; k++){
        float wi = fmaxf(fminf(c.phx[k], tb.z) - fmaxf(c.plx[k], tb.x), 0.f);
        float hi = fminf(c.phy[k], tb.w) - fmaxf(c.ply[k], tb.y);
        vmax[k] = fmaxf(vmax[k], fmaf(wi, hi, -ar3));
      }
    }
  }
  #pragma unroll
  for (int k = 0; k < 2; k++){
    if (un[k] && !(vmax[k] > c.ap3[k])){ acc[2] += -clogf_(1.f - c.so[k]); acc[4] += c.so[k]*c.so[k]; }
  }
}

// ------------------------------------------------------------------ THE kernel: fully block-local, one launch
__global__ __launch_bounds__(TPB, 2) void k_all(
    const float* __restrict__ x0, const float* __restrict__ x1, const float* __restrict__ x2,
    const float* __restrict__ labels, float* __restrict__ gout)
{
  __shared__ float4 s_box[NT];
  __shared__ float  s_ar3[NT];
  __shared__ __align__(4) unsigned char s_mbit[CELLS];
  __shared__ float  s_lab[NT][5];
  __shared__ int    s_key[NT];
  __shared__ int    s_win[NT];
  __shared__ float  s_red[5];
  __shared__ int    s_cnt;
  __shared__ int    s_last;

  int bid = blockIdx.x, tid = threadIdx.x;
  if (tid < 5) s_red[tid] = 0.f;
  float acc[5] = {0.f,0.f,0.f,0.f,0.f};

  if (bid < MATCHB){
    // ================= MATCH BLOCK (one per b): self-contained =================
    int b = bid;
    int key = -1;
    if (tid < NT){
      const float* lp = labels + (b*NT + tid)*5;
      float a0 = lp[0], a1 = lp[1], a2 = lp[2], a3 = lp[3], a4 = lp[4];
      s_lab[tid][0]=a0; s_lab[tid][1]=a1; s_lab[tid][2]=a2; s_lab[tid][3]=a3; s_lab[tid][4]=a4;
      bool valid = (a0+a1+a2+a3+a4) > 0.0f;
      if (valid){
        int bi = ciou_argmax((a2-a0)*0.125f, (a3-a1)*0.125f);
        int Lm = bi/3;
        const float invsA[3] = {0.125f, 0.0625f, 0.03125f};
        const int   fsA[3]   = {76, 38, 19};
        float invs = invsA[Lm]; int fs = fsA[Lm];
        float tx = (a2+a0)*(0.5f*invs), ty = (a3+a1)*(0.5f*invs);
        int ii = (int)tx; ii = ii < 0 ? 0 : (ii > fs-1 ? fs-1 : ii);
        int jj = (int)ty; jj = jj < 0 ? 0 : (jj > fs-1 ? fs-1 : jj);
        int cc = (bi - 3*Lm)*fs*fs + jj*fs + ii;      // < 17328 < 2^16
        key = (Lm << 16) | cc;
      }
      s_key[tid] = key;
    }
    __syncthreads();
    if (tid < NT){
      int w = 0;
      if (key >= 0){                                   // winner = last t with this (level,cell)
        w = 1;
        for (int t2 = tid+1; t2 < NT; t2++) if (s_key[t2] == key){ w = 0; break; }
      }
      s_win[tid] = w;
    }
    __syncthreads();
    int wrp = tid >> 5, lane = tid & 31;               // 16 warps
    for (int t = wrp; t < NT; t += 16){                // warp-uniform entry selection
      if (!s_win[t]) continue;
      int k2 = s_key[t];
      int Lm = k2 >> 16, cc = k2 & 0xFFFF;
      const int   fsqA[3]  = {FSQ0, FSQ1, FSQ2};
      const float invsA[3] = {0.125f, 0.0625f, 0.03125f};
      const float* x = (Lm==0) ? x0 : ((Lm==1) ? x1 : x2);
      int FSQ = fsqA[Lm];
      float invs = invsA[Lm];
      int a = cc/FSQ, cell = cc - a*FSQ;
      const float* xp = x + (b*255 + a*85)*FSQ + cell;
      float a0 = s_lab[t][0], a1 = s_lab[t][1], a2 = s_lab[t][2], a3 = s_lab[t][3], a4 = s_lab[t][4];
      float tx = (a2+a0)*(0.5f*invs), ty = (a3+a1)*(0.5f*invs);
      float tw = (a2-a0)*invs,        th = (a3-a1)*invs;
      float scl = sqrtf(2.0f - tw*th/(float)FSQ);
      int cl = (int)a4;
      for (int c = lane; c < NCLS; c += 32){
        float s = sigf_(__ldg(xp + (5+c)*FSQ));
        if (c == cl){ acc[3] += -clogf_(s);       float er = s-1.f; acc[4] += er*er; }
        else        { acc[3] += -clogf_(1.f - s); acc[4] += s*s; }
      }
      if (lane == 0){
        float AW = cANW[3*Lm+a]*invs, AH = cANH[3*Lm+a]*invs;
        float o0 = __ldg(xp), o1 = __ldg(xp+FSQ), o2 = __ldg(xp+2*FSQ), o3 = __ldg(xp+3*FSQ);
        float s0 = sigf_(o0), s1 = sigf_(o1);
        float fx = tx - truncf(tx), fy = ty - truncf(ty);
        float lw = __logf(tw/AW + 1e-16f), lh = __logf(th/AH + 1e-16f);
        float w2 = scl*scl;
        acc[0] += w2*( -(fx*clogf_(s0) + (1.f-fx)*clogf_(1.f-s0))
                       -(fy*clogf_(s1) + (1.f-fy)*clogf_(1.f-s1)) );
        float dx = (o2-lw)*scl, dy = (o3-lh)*scl;
        acc[1] += 0.5f*(dx*dx + dy*dy);
        float e0 = s0-fx, e1 = s1-fy;
        acc[4] += e0*e0 + e1*e1 + dx*dx + dy*dy;
      }
    }
  } else {
    // ================= MAIN BLOCK: self-contained prep + obj loss =================
    int mbid = bid - MATCHB;
    int Lv, b, chunk;
    if (mbid < NB*CH0)            { Lv = 0; b = mbid/CH0;                    chunk = mbid - b*CH0; }
    else if (mbid < NB*(CH0+CH1)) { int r = mbid - NB*CH0;       Lv = 1; b = r/CH1; chunk = r - b*CH1; }
    else                          { int r = mbid - NB*(CH0+CH1); Lv = 2; b = r/CH2; chunk = r - b*CH2; }

    // phase A: in-block truth prep (bitmap zero + boxes + argmax)
    if (tid < CELLS/4) ((int*)s_mbit)[tid] = 0;        // 1024 B = 256 ints
    if (tid == 0) s_cnt = 0;
    int mi = -1;
    if (tid < NT){
      const float* lp = labels + (b*NT + tid)*5;
      float a0 = lp[0], a1 = lp[1], a2 = lp[2], a3 = lp[3], a4 = lp[4];
      bool valid = (a0+a1+a2+a3+a4) > 0.0f;
      if (valid){
        int bi = ciou_argmax((a2-a0)*0.125f, (a3-a1)*0.125f);
        float invs = (Lv==0) ? 0.125f : ((Lv==1) ? 0.0625f : 0.03125f);
        int   fs   = (Lv==0) ? 76 : ((Lv==1) ? 38 : 19);
        float tx = (a2+a0)*(0.5f*invs), ty = (a3+a1)*(0.5f*invs);
        float tw = (a2-a0)*invs,        th = (a3-a1)*invs;
        int p = atomicAdd(&s_cnt, 1);                  // order-free: feeds exact max only
        s_box[p] = make_float4(tx - tw*0.5f, ty - th*0.5f, tx + tw*0.5f, ty + th*0.5f);
        s_ar3[p] = tw*th*(1.0f/3.0f);
        if (bi/3 == Lv){
          int ii = (int)tx; ii = ii < 0 ? 0 : (ii > fs-1 ? fs-1 : ii);
          int jj = (int)ty; jj = jj < 0 ? 0 : (jj > fs-1 ? fs-1 : jj);
          mi = (bi - 3*Lv)*fs*fs + jj*fs + ii;
        }
      }
    }
    int hm = __syncthreads_or(mi >= 0);                // also fences s_box/s_cnt/bitmap-zero
    if (mi >= 0){
      int off = mi - chunk*CELLS;
      if (off >= 0 && off < CELLS) s_mbit[off] = 1;    // boolean suffices for obj path
    }
    int nv = s_cnt;

    // phase B: channel loads + pred boxes, sync (covers bitmap), ignore loop
    if (Lv == 0){
      Ctx<0,76> c; main_pre<0,76>(x0, b, chunk, c);
      __syncthreads();
      main_post<0,76>(c, nv, hm, s_box, s_ar3, s_mbit, acc);
    } else if (Lv == 1){
      Ctx<1,38> c; main_pre<1,38>(x1, b, chunk, c);
      __syncthreads();
      main_post<1,38>(c, nv, hm, s_box, s_ar3, s_mbit, acc);
    } else {
      Ctx2 c; main_pre2(x2, b, chunk, c);
      __syncthreads();
      main_post2(c, nv, hm, s_box, s_ar3, s_mbit, acc);
    }
  }

  // ================= block reduction -> per-block partial =================
  #pragma unroll
  for (int k = 0; k < 5; k++){
    float v = acc[k];
    #pragma unroll
    for (int off = 16; off > 0; off >>= 1) v += __shfl_down_sync(0xffffffffu, v, off);
    if ((tid & 31) == 0 && v != 0.f) atomicAdd(&s_red[k], v);
  }
  __syncthreads();
  if (tid < 5){ g_partial[bid][tid] = s_red[tid]; __threadfence(); }
  __syncthreads();
  if (tid == 0) s_last = (atomicAdd(&g_done, 1) == GRID-1);
  __syncthreads();

  // ================= last block: final sum, writes all of gout =================
  if (s_last){
    int wrp = tid >> 5, lane = tid & 31;
    if (wrp < 5){
      float v = 0.f;
      for (int r = lane; r < GRID; r += 32) v += __ldcg(&g_partial[r][wrp]);
      #pragma unroll
      for (int off = 16; off > 0; off >>= 1) v += __shfl_down_sync(0xffffffffu, v, off);
      if (lane == 0) s_red[wrp] = v;
    }
    __syncthreads();
    if (tid == 0){
      g_done = 0;                                      // restore invariant for next replay
      float lxy = s_red[0], lwh = s_red[1], lobj = s_red[2], lcls = s_red[3], ll2 = s_red[4];
      gout[0] = lxy + lwh + lobj + lcls;
      gout[1] = lxy; gout[2] = lwh; gout[3] = lobj; gout[4] = lcls; gout[5] = ll2;
    }
  }
}

// ------------------------------------------------------------------ launch: ONE node
extern "C" void kernel_launch(void* const* d_in, const int* in_sizes, int n_in,
                              void* d_out, int out_size)
{
  const float* x0     = (const float*)d_in[0];
  const float* x1     = (const float*)d_in[1];
  const float* x2     = (const float*)d_in[2];
  const float* labels = (const float*)d_in[3];
  float* gout = (float*)d_out;
  (void)in_sizes; (void)n_in; (void)out_size;

  k_all<<<GRID, TPB>>>(x0, x1, x2, labels, gout);
}

// round 14
// speedup vs baseline: 1.0553x; 1.0553x over previous
#include <cuda_runtime.h>
#include <math.h>

#define NB 16
#define NT 60
#define NCLS 80

__constant__ float cANW[9] = {12.f,19.f,40.f,36.f,76.f,72.f,142.f,192.f,459.f};
__constant__ float cANH[9] = {16.f,36.f,28.f,75.f,55.f,146.f,110.f,243.f,401.f};
// atan(w/h) per anchor — scale-invariant constants (<5e-6 abs err; argmax gaps O(1e-2))
__constant__ float cATAN[9] = {0.6435011f, 0.4856221f, 0.9600704f,
                               0.4475200f, 0.9443511f, 0.4581533f,
                               0.9117062f, 0.6686896f, 0.8527381f};

#define FSQ0 5776
#define FSQ1 1444
#define FSQ2 361

#define TPB 256
#define CELLS 1024                   /* cells per main block (CPT=4, measured best) */
#define CH0 17
#define CH1 5
#define CH2 2
#define MATCHB 16                    /* one match block per batch b */
#define MAINB (NB*(CH0+CH1+CH2))     /* 384 */
#define GRID (MATCHB + MAINB)        /* 400 */

__device__ float g_partial[GRID][5]; // fully rewritten each run — replay safe
__device__ int   g_done;             // reset to 0 by last block each run

__device__ __forceinline__ float clogf_(float v){ return fmaxf(__logf(v), -100.0f); }
__device__ __forceinline__ float sigf_(float v){ return __fdividef(1.0f, 1.0f + __expf(-v)); }

// CIoU argmax over 9 anchors at L0 scale (scale-invariant across levels)
__device__ __forceinline__ int ciou_argmax(float tw, float th){
  float at_t = atanf(tw/th);
  float twth = tw*th;
  float best = -3.0e38f; int bi = 0;
  #pragma unroll
  for (int k = 0; k < 9; k++){
    float wb = cANW[k]*0.125f, hb = cANH[k]*0.125f;
    float ai = fminf(tw,wb)*fminf(th,hb);
    float au = twth + wb*hb - ai;
    float iou = ai/au;
    float mw = fmaxf(tw,wb), mh = fmaxf(th,hb);
    float c2 = mw*mw + mh*mh + 1e-16f;
    float dw = tw-wb, dh = th-hb;
    float rho2 = (dw*dw + dh*dh)*0.25f;
    float da = at_t - cATAN[k];
    float v = 0.40528473455296503f*(da*da);      // 4/pi^2
    float alpha = v/(1.0f - iou + v);
    float ciou = iou - (rho2/c2 + v*alpha);
    if (ciou > best){ best = ciou; bi = k; }     // first-max == jnp.argmax
  }
  return bi;
}

// ------------------------------------------------------------------ main-path context (corner form, 4 cells/thread)
template<int L, int FS>
struct Ctx {
  float so[4], plx[4], ply[4], phx[4], phy[4], ap3[4];
  int base;
};

template<int L, int FS>
__device__ __forceinline__ void main_pre(const float* __restrict__ x, int b, int chunk, Ctx<L,FS>& c){
  constexpr int FSQ = FS*FS;
  constexpr float invs = (L==0) ? 0.125f : 0.0625f;
  c.base = chunk*CELLS + (int)threadIdx.x*4;
  #pragma unroll
  for (int k = 0; k < 4; k++){
    c.so[k] = 0.f; c.plx[k] = 3e4f; c.phx[k] = 3e4f; c.ply[k] = 0.f; c.phy[k] = 0.f; c.ap3[k] = 1.f;
  }
  if (c.base < 3*FSQ){
    int a = c.base/FSQ, cell = c.base - a*FSQ;
    int j0 = cell / FS, i0 = cell - j0*FS;       // FS%4==0 => 4 cells share a row
    const float* xp = x + (b*255 + a*85)*FSQ + cell;
    float4 O0 = __ldg((const float4*)(xp));
    float4 O1 = __ldg((const float4*)(xp+FSQ));
    float4 O2 = __ldg((const float4*)(xp+2*FSQ));
    float4 O3 = __ldg((const float4*)(xp+3*FSQ));
    float4 O4 = __ldg((const float4*)(xp+4*FSQ));
    float AW = cANW[3*L+a]*invs, AH = cANH[3*L+a]*invs;
    float o0a[4] = {O0.x,O0.y,O0.z,O0.w};
    float o1a[4] = {O1.x,O1.y,O1.z,O1.w};
    float o2a[4] = {O2.x,O2.y,O2.z,O2.w};
    float o3a[4] = {O3.x,O3.y,O3.z,O3.w};
    float o4a[4] = {O4.x,O4.y,O4.z,O4.w};
    float fj = (float)j0;
    #pragma unroll
    for (int k = 0; k < 4; k++){
      c.so[k] = sigf_(o4a[k]);
      float pw = __expf(o2a[k])*AW, ph = __expf(o3a[k])*AH;
      float px = (float)(i0+k) + sigf_(o0a[k]);
      float py = fj + sigf_(o1a[k]);
      float hw = 0.5f*pw, hh = 0.5f*ph;
      c.plx[k] = px-hw; c.phx[k] = px+hw; c.ply[k] = py-hh; c.phy[k] = py+hh;
      c.ap3[k] = pw*ph*(1.0f/3.0f);
    }
  }
}

template<int L, int FS>
__device__ __forceinline__ void main_post(const Ctx<L,FS>& c, int nv, int hm,
    const float4* __restrict__ s_box, const float* __restrict__ s_ar3,
    const unsigned char* __restrict__ s_mbit, float* acc){
  constexpr int FSQ = FS*FS;
  bool un[4] = {false,false,false,false};
  if (c.base < 3*FSQ){
    uchar4 mb = *(const uchar4*)(s_mbit + threadIdx.x*4);  // in-chunk offset = tid*4
    unsigned char m[4] = {mb.x, mb.y, mb.z, mb.w};
    #pragma unroll
    for (int k = 0; k < 4; k++){
      if (m[k]){ acc[2] += -clogf_(c.so[k]); float e = c.so[k]-1.f; acc[4] += e*e; }
      else un[k] = true;
    }
  }
  float vmax[4] = {-1e30f,-1e30f,-1e30f,-1e30f};
  if (hm){
    #pragma unroll 4
    for (int t = 0; t < nv; t++){
      float4 tb = s_box[t];
      float ar3 = s_ar3[t];
      #pragma unroll
      for (int k = 0; k < 4; k++){
        float wi = fmaxf(fminf(c.phx[k], tb.z) - fmaxf(c.plx[k], tb.x), 0.f);
        float hi = fminf(c.phy[k], tb.w) - fmaxf(c.ply[k], tb.y);
        vmax[k] = fmaxf(vmax[k], fmaf(wi, hi, -ar3));   // iou>.5 <=> ai-at/3 > ap/3
      }
    }
  }
  #pragma unroll
  for (int k = 0; k < 4; k++){
    if (un[k] && !(vmax[k] > c.ap3[k])){ acc[2] += -clogf_(1.f - c.so[k]); acc[4] += c.so[k]*c.so[k]; }
  }
}

// scalar variant for L2 (FSQ=361, not divisible by 4)
struct Ctx2 {
  float so[4], plx[4], ply[4], phx[4], phy[4], ap3[4];
  int base;
};

__device__ __forceinline__ void main_pre2(const float* __restrict__ x, int b, int chunk, Ctx2& c){
  constexpr int FSQ = FSQ2;
  constexpr float invs = 0.03125f;
  c.base = chunk*CELLS + (int)threadIdx.x;
  #pragma unroll
  for (int k = 0; k < 4; k++){
    int cc = c.base + k*TPB;
    c.so[k] = 0.f; c.plx[k] = 3e4f; c.phx[k] = 3e4f; c.ply[k] = 0.f; c.phy[k] = 0.f; c.ap3[k] = 1.f;
    if (cc < 3*FSQ){
      int a = cc/FSQ, cell = cc - a*FSQ;
      const float* xp = x + (b*255 + a*85)*FSQ + cell;
      c.so[k] = sigf_(__ldg(xp + 4*FSQ));
      float AW = cANW[6+a]*invs, AH = cANH[6+a]*invs;
      float pw = __expf(__ldg(xp+2*FSQ))*AW, ph = __expf(__ldg(xp+3*FSQ))*AH;
      float px = (float)(cell % 19) + sigf_(__ldg(xp));
      float py = (float)(cell / 19) + sigf_(__ldg(xp+FSQ));
      float hw = 0.5f*pw, hh = 0.5f*ph;
      c.plx[k] = px-hw; c.phx[k] = px+hw; c.ply[k] = py-hh; c.phy[k] = py+hh;
      c.ap3[k] = pw*ph*(1.0f/3.0f);
    }
  }
}

__device__ __forceinline__ void main_post2(const Ctx2& c, int nv, int hm,
    const float4* __restrict__ s_box, const float* __restrict__ s_ar3,
    const unsigned char* __restrict__ s_mbit, float* acc){
  constexpr int FSQ = FSQ2;
  bool un[4] = {false,false,false,false};
  #pragma unroll
  for (int k = 0; k < 4; k++){
    int cc = c.base + k*TPB;
    if (cc < 3*FSQ){
      if (s_mbit[(int)threadIdx.x + k*TPB]){ acc[2] += -clogf_(c.so[k]); float e = c.so[k]-1.f; acc[4] += e*e; }
      else un[k] = true;
    }
  }
  float vmax[4] = {-1e30f,-1e30f,-1e30f,-1e30f};
  if (hm){
    #pragma unroll 4
    for (int t = 0; t < nv; t++){
      float4 tb = s_box[t];
      float ar3 = s_ar3[t];
      #pragma unroll
      for (int k = 0; k < 4; k++){
        float wi = fmaxf(fminf(c.phx[k], tb.z) - fmaxf(c.plx[k], tb.x), 0.f);
        float hi = fminf(c.phy[k], tb.w) - fmaxf(c.ply[k], tb.y);
        vmax[k] = fmaxf(vmax[k], fmaf(wi, hi, -ar3));
      }
    }
  }
  #pragma unroll
  for (int k = 0; k < 4; k++){
    if (un[k] && !(vmax[k] > c.ap3[k])){ acc[2] += -clogf_(1.f - c.so[k]); acc[4] += c.so[k]*c.so[k]; }
  }
}

// ------------------------------------------------------------------ THE kernel: fully block-local, one launch
__global__ __launch_bounds__(TPB) void k_all(
    const float* __restrict__ x0, const float* __restrict__ x1, const float* __restrict__ x2,
    const float* __restrict__ labels, float* __restrict__ gout)
{
  __shared__ float4 s_box[NT];
  __shared__ float  s_ar3[NT];
  __shared__ __align__(4) unsigned char s_mbit[CELLS];
  __shared__ float  s_lab[NT][5];
  __shared__ int    s_key[NT];
  __shared__ int    s_win[NT];
  __shared__ float  s_red[5];
  __shared__ int    s_cnt;
  __shared__ int    s_last;

  int bid = blockIdx.x, tid = threadIdx.x;
  if (tid < 5) s_red[tid] = 0.f;
  float acc[5] = {0.f,0.f,0.f,0.f,0.f};

  if (bid < MATCHB){
    // ================= MATCH BLOCK (one per b): self-contained =================
    int b = bid;
    int key = -1;
    if (tid < NT){
      const float* lp = labels + (b*NT + tid)*5;
      float a0 = lp[0], a1 = lp[1], a2 = lp[2], a3 = lp[3], a4 = lp[4];
      s_lab[tid][0]=a0; s_lab[tid][1]=a1; s_lab[tid][2]=a2; s_lab[tid][3]=a3; s_lab[tid][4]=a4;
      bool valid = (a0+a1+a2+a3+a4) > 0.0f;
      if (valid){
        int bi = ciou_argmax((a2-a0)*0.125f, (a3-a1)*0.125f);
        int Lm = bi/3;
        const float invsA[3] = {0.125f, 0.0625f, 0.03125f};
        const int   fsA[3]   = {76, 38, 19};
        float invs = invsA[Lm]; int fs = fsA[Lm];
        float tx = (a2+a0)*(0.5f*invs), ty = (a3+a1)*(0.5f*invs);
        int ii = (int)tx; ii = ii < 0 ? 0 : (ii > fs-1 ? fs-1 : ii);
        int jj = (int)ty; jj = jj < 0 ? 0 : (jj > fs-1 ? fs-1 : jj);
        int cc = (bi - 3*Lm)*fs*fs + jj*fs + ii;      // < 17328 < 2^16
        key = (Lm << 16) | cc;
      }
      s_key[tid] = key;
    }
    __syncthreads();
    if (tid < NT){
      int w = 0;
      if (key >= 0){                                   // winner = last t with this (level,cell)
        w = 1;
        for (int t2 = tid+1; t2 < NT; t2++) if (s_key[t2] == key){ w = 0; break; }
      }
      s_win[tid] = w;
    }
    __syncthreads();
    int wrp = tid >> 5, lane = tid & 31;
    for (int t = wrp; t < NT; t += 8){                 // warp-uniform entry selection
      if (!s_win[t]) continue;
      int k2 = s_key[t];
      int Lm = k2 >> 16, cc = k2 & 0xFFFF;
      const int   fsqA[3]  = {FSQ0, FSQ1, FSQ2};
      const float invsA[3] = {0.125f, 0.0625f, 0.03125f};
      const float* x = (Lm==0) ? x0 : ((Lm==1) ? x1 : x2);
      int FSQ = fsqA[Lm];
      float invs = invsA[Lm];
      int a = cc/FSQ, cell = cc - a*FSQ;
      const float* xp = x + (b*255 + a*85)*FSQ + cell;
      float a0 = s_lab[t][0], a1 = s_lab[t][1], a2 = s_lab[t][2], a3 = s_lab[t][3], a4 = s_lab[t][4];
      float tx = (a2+a0)*(0.5f*invs), ty = (a3+a1)*(0.5f*invs);
      float tw = (a2-a0)*invs,        th = (a3-a1)*invs;
      float scl = sqrtf(2.0f - tw*th/(float)FSQ);
      int cl = (int)a4;
      for (int c = lane; c < NCLS; c += 32){
        float s = sigf_(__ldg(xp + (5+c)*FSQ));
        if (c == cl){ acc[3] += -clogf_(s);       float er = s-1.f; acc[4] += er*er; }
        else        { acc[3] += -clogf_(1.f - s); acc[4] += s*s; }
      }
      if (lane == 0){
        float AW = cANW[3*Lm+a]*invs, AH = cANH[3*Lm+a]*invs;
        float o0 = __ldg(xp), o1 = __ldg(xp+FSQ), o2 = __ldg(xp+2*FSQ), o3 = __ldg(xp+3*FSQ);
        float s0 = sigf_(o0), s1 = sigf_(o1);
        float fx = tx - truncf(tx), fy = ty - truncf(ty);
        float lw = __logf(tw/AW + 1e-16f), lh = __logf(th/AH + 1e-16f);
        float w2 = scl*scl;
        acc[0] += w2*( -(fx*clogf_(s0) + (1.f-fx)*clogf_(1.f-s0))
                       -(fy*clogf_(s1) + (1.f-fy)*clogf_(1.f-s1)) );
        float dx = (o2-lw)*scl, dy = (o3-lh)*scl;
        acc[1] += 0.5f*(dx*dx + dy*dy);
        float e0 = s0-fx, e1 = s1-fy;
        acc[4] += e0*e0 + e1*e1 + dx*dx + dy*dy;
      }
    }
  } else {
    // ================= MAIN BLOCK: self-contained prep + obj loss =================
    int mbid = bid - MATCHB;
    int Lv, b, chunk;
    if (mbid < NB*CH0)            { Lv = 0; b = mbid/CH0;                    chunk = mbid - b*CH0; }
    else if (mbid < NB*(CH0+CH1)) { int r = mbid - NB*CH0;       Lv = 1; b = r/CH1; chunk = r - b*CH1; }
    else                          { int r = mbid - NB*(CH0+CH1); Lv = 2; b = r/CH2; chunk = r - b*CH2; }

    // phase A: in-block truth prep (bitmap zero + boxes + argmax)
    ((int*)s_mbit)[tid] = 0;                           // 256 ints = 1024 B
    if (tid == 0) s_cnt = 0;
    int mi = -1;
    if (tid < NT){
      const float* lp = labels + (b*NT + tid)*5;
      float a0 = lp[0], a1 = lp[1], a2 = lp[2], a3 = lp[3], a4 = lp[4];
      bool valid = (a0+a1+a2+a3+a4) > 0.0f;
      if (valid){
        int bi = ciou_argmax((a2-a0)*0.125f, (a3-a1)*0.125f);
        float invs = (Lv==0) ? 0.125f : ((Lv==1) ? 0.0625f : 0.03125f);
        int   fs   = (Lv==0) ? 76 : ((Lv==1) ? 38 : 19);
        float tx = (a2+a0)*(0.5f*invs), ty = (a3+a1)*(0.5f*invs);
        float tw = (a2-a0)*invs,        th = (a3-a1)*invs;
        int p = atomicAdd(&s_cnt, 1);                  // order-free: feeds exact max only
        s_box[p] = make_float4(tx - tw*0.5f, ty - th*0.5f, tx + tw*0.5f, ty + th*0.5f);
        s_ar3[p] = tw*th*(1.0f/3.0f);
        if (bi/3 == Lv){
          int ii = (int)tx; ii = ii < 0 ? 0 : (ii > fs-1 ? fs-1 : ii);
          int jj = (int)ty; jj = jj < 0 ? 0 : (jj > fs-1 ? fs-1 : jj);
          mi = (bi - 3*Lv)*fs*fs + jj*fs + ii;
        }
      }
    }
    int hm = __syncthreads_or(mi >= 0);                // also fences s_box/s_cnt/bitmap-zero
    if (mi >= 0){
      int off = mi - chunk*CELLS;
      if (off >= 0 && off < CELLS) s_mbit[off] = 1;    // boolean suffices for obj path
    }
    int nv = s_cnt;

    // phase B: channel loads + pred boxes, sync (covers bitmap), ignore loop
    if (Lv == 0){
      Ctx<0,76> c; main_pre<0,76>(x0, b, chunk, c);
      __syncthreads();
      main_post<0,76>(c, nv, hm, s_box, s_ar3, s_mbit, acc);
    } else if (Lv == 1){
      Ctx<1,38> c; main_pre<1,38>(x1, b, chunk, c);
      __syncthreads();
      main_post<1,38>(c, nv, hm, s_box, s_ar3, s_mbit, acc);
    } else {
      Ctx2 c; main_pre2(x2, b, chunk, c);
      __syncthreads();
      main_post2(c, nv, hm, s_box, s_ar3, s_mbit, acc);
    }
  }

  // ================= block reduction -> per-block partial =================
  #pragma unroll
  for (int k = 0; k < 5; k++){
    float v = acc[k];
    #pragma unroll
    for (int off = 16; off > 0; off >>= 1) v += __shfl_down_sync(0xffffffffu, v, off);
    if ((tid & 31) == 0 && v != 0.f) atomicAdd(&s_red[k], v);
  }
  __syncthreads();
  if (tid < 5){ g_partial[bid][tid] = s_red[tid]; __threadfence(); }
  __syncthreads();
  if (tid == 0) s_last = (atomicAdd(&g_done, 1) == GRID-1);
  __syncthreads();

  // ================= last block: final sum, writes all of gout =================
  if (s_last){
    int wrp = tid >> 5, lane = tid & 31;
    if (wrp < 5){
      float v = 0.f;
      for (int r = lane; r < GRID; r += 32) v += __ldcg(&g_partial[r][wrp]);
      #pragma unroll
      for (int off = 16; off > 0; off >>= 1) v += __shfl_down_sync(0xffffffffu, v, off);
      if (lane == 0) s_red[wrp] = v;
    }
    __syncthreads();
    if (tid == 0){
      g_done = 0;                                      // restore invariant for next replay
      float lxy = s_red[0], lwh = s_red[1], lobj = s_red[2], lcls = s_red[3], ll2 = s_red[4];
      gout[0] = lxy + lwh + lobj + lcls;
      gout[1] = lxy; gout[2] = lwh; gout[3] = lobj; gout[4] = lcls; gout[5] = ll2;
    }
  }
}

// ------------------------------------------------------------------ launch: ONE node
extern "C" void kernel_launch(void* const* d_in, const int* in_sizes, int n_in,
                              void* d_out, int out_size)
{
  const float* x0     = (const float*)d_in[0];
  const float* x1     = (const float*)d_in[1];
  const float* x2     = (const float*)d_in[2];
  const float* labels = (const float*)d_in[3];
  float* gout = (float*)d_out;
  (void)in_sizes; (void)n_in; (void)out_size;

  k_all<<<GRID, TPB>>>(x0, x1, x2, labels, gout);
}

// round 15
// speedup vs baseline: 1.0666x; 1.0107x over previous
#include <cuda_runtime.h>
#include <math.h>

#define NB 16
#define NT 60
#define NCLS 80

__constant__ float cANW[9] = {12.f,19.f,40.f,36.f,76.f,72.f,142.f,192.f,459.f};
__constant__ float cANH[9] = {16.f,36.f,28.f,75.f,55.f,146.f,110.f,243.f,401.f};
// atan(w/h) per anchor — scale-invariant constants (<5e-6 abs err; argmax gaps O(1e-2))
__constant__ float cATAN[9] = {0.6435011f, 0.4856221f, 0.9600704f,
                               0.4475200f, 0.9443511f, 0.4581533f,
                               0.9117062f, 0.6686896f, 0.8527381f};

#define FSQ0 5776
#define FSQ1 1444
#define FSQ2 361

#define TPB 256
#define CELLS 1024                   /* cells per main block (CPT=4, measured best) */
#define CH0 17
#define CH1 5
#define CH2 2
#define MATCHB 16                    /* one match block per batch b */
#define MAINB (NB*(CH0+CH1+CH2))     /* 384 */
#define GRID (MATCHB + MAINB)        /* 400 */

__device__ float g_partial[GRID][5]; // fully rewritten each run — replay safe
__device__ int   g_done;             // reset to 0 by last block each run

__device__ __forceinline__ float clogf_(float v){ return fmaxf(__logf(v), -100.0f); }
__device__ __forceinline__ float sigf_(float v){ return __fdividef(1.0f, 1.0f + __expf(-v)); }

// CIoU argmax over 9 anchors at L0 scale (scale-invariant across levels)
__device__ __forceinline__ int ciou_argmax(float tw, float th){
  float at_t = atanf(tw/th);
  float twth = tw*th;
  float best = -3.0e38f; int bi = 0;
  #pragma unroll
  for (int k = 0; k < 9; k++){
    float wb = cANW[k]*0.125f, hb = cANH[k]*0.125f;
    float ai = fminf(tw,wb)*fminf(th,hb);
    float au = twth + wb*hb - ai;
    float iou = ai/au;
    float mw = fmaxf(tw,wb), mh = fmaxf(th,hb);
    float c2 = mw*mw + mh*mh + 1e-16f;
    float dw = tw-wb, dh = th-hb;
    float rho2 = (dw*dw + dh*dh)*0.25f;
    float da = at_t - cATAN[k];
    float v = 0.40528473455296503f*(da*da);      // 4/pi^2
    float alpha = v/(1.0f - iou + v);
    float ciou = iou - (rho2/c2 + v*alpha);
    if (ciou > best){ best = ciou; bi = k; }     // first-max == jnp.argmax
  }
  return bi;
}

// ------------------------------------------------------------------ main-path context (corner form, 4 cells/thread)
template<int L, int FS>
struct Ctx {
  float so[4], plx[4], ply[4], phx[4], phy[4], ap3[4];
  int base;
};

template<int L, int FS>
__device__ __forceinline__ void main_pre(const float* __restrict__ x, int b, int chunk, Ctx<L,FS>& c){
  constexpr int FSQ = FS*FS;
  constexpr float invs = (L==0) ? 0.125f : 0.0625f;
  c.base = chunk*CELLS + (int)threadIdx.x*4;
  #pragma unroll
  for (int k = 0; k < 4; k++){
    c.so[k] = 0.f; c.plx[k] = 3e4f; c.phx[k] = 3e4f; c.ply[k] = 0.f; c.phy[k] = 0.f; c.ap3[k] = 1.f;
  }
  if (c.base < 3*FSQ){
    int a = c.base/FSQ, cell = c.base - a*FSQ;
    int j0 = cell / FS, i0 = cell - j0*FS;       // FS%4==0 => 4 cells share a row
    const float* xp = x + (b*255 + a*85)*FSQ + cell;
    float4 O0 = __ldg((const float4*)(xp));
    float4 O1 = __ldg((const float4*)(xp+FSQ));
    float4 O2 = __ldg((const float4*)(xp+2*FSQ));
    float4 O3 = __ldg((const float4*)(xp+3*FSQ));
    float4 O4 = __ldg((const float4*)(xp+4*FSQ));
    float AW = cANW[3*L+a]*invs, AH = cANH[3*L+a]*invs;
    float o0a[4] = {O0.x,O0.y,O0.z,O0.w};
    float o1a[4] = {O1.x,O1.y,O1.z,O1.w};
    float o2a[4] = {O2.x,O2.y,O2.z,O2.w};
    float o3a[4] = {O3.x,O3.y,O3.z,O3.w};
    float o4a[4] = {O4.x,O4.y,O4.z,O4.w};
    float fj = (float)j0;
    #pragma unroll
    for (int k = 0; k < 4; k++){
      c.so[k] = sigf_(o4a[k]);
      float pw = __expf(o2a[k])*AW, ph = __expf(o3a[k])*AH;
      float px = (float)(i0+k) + sigf_(o0a[k]);
      float py = fj + sigf_(o1a[k]);
      float hw = 0.5f*pw, hh = 0.5f*ph;
      c.plx[k] = px-hw; c.phx[k] = px+hw; c.ply[k] = py-hh; c.phy[k] = py+hh;
      c.ap3[k] = pw*ph*(1.0f/3.0f);
    }
  }
}

template<int L, int FS>
__device__ __forceinline__ void main_post(const Ctx<L,FS>& c, int nv, int hm,
    const float4* __restrict__ s_box, const float* __restrict__ s_ar3,
    const unsigned char* __restrict__ s_mbit, float* acc){
  constexpr int FSQ = FS*FS;
  bool un[4] = {false,false,false,false};
  if (c.base < 3*FSQ){
    uchar4 mb = *(const uchar4*)(s_mbit + threadIdx.x*4);  // in-chunk offset = tid*4
    unsigned char m[4] = {mb.x, mb.y, mb.z, mb.w};
    #pragma unroll
    for (int k = 0; k < 4; k++){
      if (m[k]){ acc[2] += -clogf_(c.so[k]); float e = c.so[k]-1.f; acc[4] += e*e; }
      else un[k] = true;
    }
  }
  float vmax[4] = {-1e30f,-1e30f,-1e30f,-1e30f};
  if (hm){
    #pragma unroll 4
    for (int t = 0; t < nv; t++){
      float4 tb = s_box[t];
      float ar3 = s_ar3[t];
      #pragma unroll
      for (int k = 0; k < 4; k++){
        float wi = fmaxf(fminf(c.phx[k], tb.z) - fmaxf(c.plx[k], tb.x), 0.f);
        float hi = fminf(c.phy[k], tb.w) - fmaxf(c.ply[k], tb.y);
        vmax[k] = fmaxf(vmax[k], fmaf(wi, hi, -ar3));   // iou>.5 <=> ai-at/3 > ap/3
      }
    }
  }
  #pragma unroll
  for (int k = 0; k < 4; k++){
    if (un[k] && !(vmax[k] > c.ap3[k])){ acc[2] += -clogf_(1.f - c.so[k]); acc[4] += c.so[k]*c.so[k]; }
  }
}

// scalar variant for L2 (FSQ=361, not divisible by 4)
struct Ctx2 {
  float so[4], plx[4], ply[4], phx[4], phy[4], ap3[4];
  int base;
};

__device__ __forceinline__ void main_pre2(const float* __restrict__ x, int b, int chunk, Ctx2& c){
  constexpr int FSQ = FSQ2;
  constexpr float invs = 0.03125f;
  c.base = chunk*CELLS + (int)threadIdx.x;
  #pragma unroll
  for (int k = 0; k < 4; k++){
    int cc = c.base + k*TPB;
    c.so[k] = 0.f; c.plx[k] = 3e4f; c.phx[k] = 3e4f; c.ply[k] = 0.f; c.phy[k] = 0.f; c.ap3[k] = 1.f;
    if (cc < 3*FSQ){
      int a = cc/FSQ, cell = cc - a*FSQ;
      const float* xp = x + (b*255 + a*85)*FSQ + cell;
      c.so[k] = sigf_(__ldg(xp + 4*FSQ));
      float AW = cANW[6+a]*invs, AH = cANH[6+a]*invs;
      float pw = __expf(__ldg(xp+2*FSQ))*AW, ph = __expf(__ldg(xp+3*FSQ))*AH;
      float px = (float)(cell % 19) + sigf_(__ldg(xp));
      float py = (float)(cell / 19) + sigf_(__ldg(xp+FSQ));
      float hw = 0.5f*pw, hh = 0.5f*ph;
      c.plx[k] = px-hw; c.phx[k] = px+hw; c.ply[k] = py-hh; c.phy[k] = py+hh;
      c.ap3[k] = pw*ph*(1.0f/3.0f);
    }
  }
}

__device__ __forceinline__ void main_post2(const Ctx2& c, int nv, int hm,
    const float4* __restrict__ s_box, const float* __restrict__ s_ar3,
    const unsigned char* __restrict__ s_mbit, float* acc){
  constexpr int FSQ = FSQ2;
  bool un[4] = {false,false,false,false};
  #pragma unroll
  for (int k = 0; k < 4; k++){
    int cc = c.base + k*TPB;
    if (cc < 3*FSQ){
      if (s_mbit[(int)threadIdx.x + k*TPB]){ acc[2] += -clogf_(c.so[k]); float e = c.so[k]-1.f; acc[4] += e*e; }
      else un[k] = true;
    }
  }
  float vmax[4] = {-1e30f,-1e30f,-1e30f,-1e30f};
  if (hm){
    #pragma unroll 4
    for (int t = 0; t < nv; t++){
      float4 tb = s_box[t];
      float ar3 = s_ar3[t];
      #pragma unroll
      for (int k = 0; k < 4; k++){
        float wi = fmaxf(fminf(c.phx[k], tb.z) - fmaxf(c.plx[k], tb.x), 0.f);
        float hi = fminf(c.phy[k], tb.w) - fmaxf(c.ply[k], tb.y);
        vmax[k] = fmaxf(vmax[k], fmaf(wi, hi, -ar3));
      }
    }
  }
  #pragma unroll
  for (int k = 0; k < 4; k++){
    if (un[k] && !(vmax[k] > c.ap3[k])){ acc[2] += -clogf_(1.f - c.so[k]); acc[4] += c.so[k]*c.so[k]; }
  }
}

// ------------------------------------------------------------------ THE kernel: fully block-local, one launch
__global__ __launch_bounds__(TPB) void k_all(
    const float* __restrict__ x0, const float* __restrict__ x1, const float* __restrict__ x2,
    const float* __restrict__ labels, float* __restrict__ gout)
{
  __shared__ float4 s_box[NT];
  __shared__ float  s_ar3[NT];
  __shared__ __align__(4) unsigned char s_mbit[CELLS];
  __shared__ float  s_lab[NT][5];
  __shared__ int    s_key[NT];
  __shared__ int    s_win[NT];
  __shared__ float  s_red[5];
  __shared__ int    s_cnt;
  __shared__ int    s_last;

  int bid = blockIdx.x, tid = threadIdx.x;
  if (tid < 5) s_red[tid] = 0.f;
  float acc[5] = {0.f,0.f,0.f,0.f,0.f};

  if (bid < MATCHB){
    // ================= MATCH BLOCK (one per b): self-contained =================
    int b = bid;
    int key = -1;
    if (tid < NT){
      const float* lp = labels + (b*NT + tid)*5;
      float a0 = lp[0], a1 = lp[1], a2 = lp[2], a3 = lp[3], a4 = lp[4];
      s_lab[tid][0]=a0; s_lab[tid][1]=a1; s_lab[tid][2]=a2; s_lab[tid][3]=a3; s_lab[tid][4]=a4;
      bool valid = (a0+a1+a2+a3+a4) > 0.0f;
      if (valid){
        int bi = ciou_argmax((a2-a0)*0.125f, (a3-a1)*0.125f);
        int Lm = bi/3;
        const float invsA[3] = {0.125f, 0.0625f, 0.03125f};
        const int   fsA[3]   = {76, 38, 19};
        float invs = invsA[Lm]; int fs = fsA[Lm];
        float tx = (a2+a0)*(0.5f*invs), ty = (a3+a1)*(0.5f*invs);
        int ii = (int)tx; ii = ii < 0 ? 0 : (ii > fs-1 ? fs-1 : ii);
        int jj = (int)ty; jj = jj < 0 ? 0 : (jj > fs-1 ? fs-1 : jj);
        int cc = (bi - 3*Lm)*fs*fs + jj*fs + ii;      // < 17328 < 2^16
        key = (Lm << 16) | cc;
      }
      s_key[tid] = key;
    }
    __syncthreads();
    if (tid < NT){
      int w = 0;
      if (key >= 0){                                   // winner = last t with this (level,cell)
        w = 1;
        for (int t2 = tid+1; t2 < NT; t2++) if (s_key[t2] == key){ w = 0; break; }
      }
      s_win[tid] = w;
    }
    __syncthreads();
    int wrp = tid >> 5, lane = tid & 31;
    for (int t = wrp; t < NT; t += 8){                 // warp-uniform entry selection
      if (!s_win[t]) continue;
      int k2 = s_key[t];
      int Lm = k2 >> 16, cc = k2 & 0xFFFF;
      const int   fsqA[3]  = {FSQ0, FSQ1, FSQ2};
      const float invsA[3] = {0.125f, 0.0625f, 0.03125f};
      const float* x = (Lm==0) ? x0 : ((Lm==1) ? x1 : x2);
      int FSQ = fsqA[Lm];
      float invs = invsA[Lm];
      int a = cc/FSQ, cell = cc - a*FSQ;
      const float* xp = x + (b*255 + a*85)*FSQ + cell;
      float a0 = s_lab[t][0], a1 = s_lab[t][1], a2 = s_lab[t][2], a3 = s_lab[t][3], a4 = s_lab[t][4];
      float tx = (a2+a0)*(0.5f*invs), ty = (a3+a1)*(0.5f*invs);
      float tw = (a2-a0)*invs,        th = (a3-a1)*invs;
      float scl = sqrtf(2.0f - tw*th/(float)FSQ);
      int cl = (int)a4;
      for (int c = lane; c < NCLS; c += 32){
        float s = sigf_(__ldg(xp + (5+c)*FSQ));
        if (c == cl){ acc[3] += -clogf_(s);       float er = s-1.f; acc[4] += er*er; }
        else        { acc[3] += -clogf_(1.f - s); acc[4] += s*s; }
      }
      if (lane == 0){
        float AW = cANW[3*Lm+a]*invs, AH = cANH[3*Lm+a]*invs;
        float o0 = __ldg(xp), o1 = __ldg(xp+FSQ), o2 = __ldg(xp+2*FSQ), o3 = __ldg(xp+3*FSQ);
        float s0 = sigf_(o0), s1 = sigf_(o1);
        float fx = tx - truncf(tx), fy = ty - truncf(ty);
        float lw = __logf(tw/AW + 1e-16f), lh = __logf(th/AH + 1e-16f);
        float w2 = scl*scl;
        acc[0] += w2*( -(fx*clogf_(s0) + (1.f-fx)*clogf_(1.f-s0))
                       -(fy*clogf_(s1) + (1.f-fy)*clogf_(1.f-s1)) );
        float dx = (o2-lw)*scl, dy = (o3-lh)*scl;
        acc[1] += 0.5f*(dx*dx + dy*dy);
        float e0 = s0-fx, e1 = s1-fy;
        acc[4] += e0*e0 + e1*e1 + dx*dx + dy*dy;
      }
    }
  } else {
    // ================= MAIN BLOCK: batch-interleaved mapping for per-SM nv balance =================
    int mbid = bid - MATCHB;
    int Lv, b, chunk;
    if (mbid < NB*CH0)            { Lv = 0; b = mbid % NB;                    chunk = mbid / NB; }
    else if (mbid < NB*(CH0+CH1)) { int r = mbid - NB*CH0;       Lv = 1; b = r % NB; chunk = r / NB; }
    else                          { int r = mbid - NB*(CH0+CH1); Lv = 2; b = r % NB; chunk = r / NB; }

    // phase A: in-block truth prep (bitmap zero + boxes + argmax)
    ((int*)s_mbit)[tid] = 0;                           // 256 ints = 1024 B
    if (tid == 0) s_cnt = 0;
    int mi = -1;
    if (tid < NT){
      const float* lp = labels + (b*NT + tid)*5;
      float a0 = lp[0], a1 = lp[1], a2 = lp[2], a3 = lp[3], a4 = lp[4];
      bool valid = (a0+a1+a2+a3+a4) > 0.0f;
      if (valid){
        int bi = ciou_argmax((a2-a0)*0.125f, (a3-a1)*0.125f);
        float invs = (Lv==0) ? 0.125f : ((Lv==1) ? 0.0625f : 0.03125f);
        int   fs   = (Lv==0) ? 76 : ((Lv==1) ? 38 : 19);
        float tx = (a2+a0)*(0.5f*invs), ty = (a3+a1)*(0.5f*invs);
        float tw = (a2-a0)*invs,        th = (a3-a1)*invs;
        int p = atomicAdd(&s_cnt, 1);                  // order-free: feeds exact max only
        s_box[p] = make_float4(tx - tw*0.5f, ty - th*0.5f, tx + tw*0.5f, ty + th*0.5f);
        s_ar3[p] = tw*th*(1.0f/3.0f);
        if (bi/3 == Lv){
          int ii = (int)tx; ii = ii < 0 ? 0 : (ii > fs-1 ? fs-1 : ii);
          int jj = (int)ty; jj = jj < 0 ? 0 : (jj > fs-1 ? fs-1 : jj);
          mi = (bi - 3*Lv)*fs*fs + jj*fs + ii;
        }
      }
    }
    int hm = __syncthreads_or(mi >= 0);                // also fences s_box/s_cnt/bitmap-zero
    if (mi >= 0){
      int off = mi - chunk*CELLS;
      if (off >= 0 && off < CELLS) s_mbit[off] = 1;    // boolean suffices for obj path
    }
    int nv = s_cnt;

    // phase B: channel loads + pred boxes, sync (covers bitmap), ignore loop
    if (Lv == 0){
      Ctx<0,76> c; main_pre<0,76>(x0, b, chunk, c);
      __syncthreads();
      main_post<0,76>(c, nv, hm, s_box, s_ar3, s_mbit, acc);
    } else if (Lv == 1){
      Ctx<1,38> c; main_pre<1,38>(x1, b, chunk, c);
      __syncthreads();
      main_post<1,38>(c, nv, hm, s_box, s_ar3, s_mbit, acc);
    } else {
      Ctx2 c; main_pre2(x2, b, chunk, c);
      __syncthreads();
      main_post2(c, nv, hm, s_box, s_ar3, s_mbit, acc);
    }
  }

  // ================= block reduction -> per-block partial =================
  #pragma unroll
  for (int k = 0; k < 5; k++){
    float v = acc[k];
    #pragma unroll
    for (int off = 16; off > 0; off >>= 1) v += __shfl_down_sync(0xffffffffu, v, off);
    if ((tid & 31) == 0 && v != 0.f) atomicAdd(&s_red[k], v);
  }
  __syncthreads();
  if (tid < 5){ g_partial[bid][tid] = s_red[tid]; __threadfence(); }
  __syncthreads();
  if (tid == 0) s_last = (atomicAdd(&g_done, 1) == GRID-1);
  __syncthreads();

  // ================= last block: final sum, writes all of gout =================
  if (s_last){
    int wrp = tid >> 5, lane = tid & 31;
    if (wrp < 5){
      float v = 0.f;
      for (int r = lane; r < GRID; r += 32) v += __ldcg(&g_partial[r][wrp]);
      #pragma unroll
      for (int off = 16; off > 0; off >>= 1) v += __shfl_down_sync(0xffffffffu, v, off);
      if (lane == 0) s_red[wrp] = v;
    }
    __syncthreads();
    if (tid == 0){
      g_done = 0;                                      // restore invariant for next replay
      float lxy = s_red[0], lwh = s_red[1], lobj = s_red[2], lcls = s_red[3], ll2 = s_red[4];
      gout[0] = lxy + lwh + lobj + lcls;
      gout[1] = lxy; gout[2] = lwh; gout[3] = lobj; gout[4] = lcls; gout[5] = ll2;
    }
  }
}

// ------------------------------------------------------------------ launch: ONE node
extern "C" void kernel_launch(void* const* d_in, const int* in_sizes, int n_in,
                              void* d_out, int out_size)
{
  const float* x0     = (const float*)d_in[0];
  const float* x1     = (const float*)d_in[1];
  const float* x2     = (const float*)d_in[2];
  const float* labels = (const float*)d_in[3];
  float* gout = (float*)d_out;
  (void)in_sizes; (void)n_in; (void)out_size;

  k_all<<<GRID, TPB>>>(x0, x1, x2, labels, gout);
}

// round 16
// speedup vs baseline: 1.0768x; 1.0096x over previous
#include <cuda_runtime.h>
#include <math.h>

#define NB 16
#define NT 60
#define NCLS 80

__constant__ float cANW[9] = {12.f,19.f,40.f,36.f,76.f,72.f,142.f,192.f,459.f};
__constant__ float cANH[9] = {16.f,36.f,28.f,75.f,55.f,146.f,110.f,243.f,401.f};
// atan(w/h) per anchor — scale-invariant constants (<5e-6 abs err; argmax gaps O(1e-2))
__constant__ float cATAN[9] = {0.6435011f, 0.4856221f, 0.9600704f,
                               0.4475200f, 0.9443511f, 0.4581533f,
                               0.9117062f, 0.6686896f, 0.8527381f};

#define FSQ0 5776
#define FSQ1 1444
#define FSQ2 361

#define TPB 256
#define CELLS 1024                   /* cells per main block (CPT=4, measured best) */
#define CH0 17
#define CH1 5
#define CH2 2
#define MATCHB 16                    /* one match block per batch b */
#define MAINB (NB*(CH0+CH1+CH2))     /* 384 */
#define GRID (MATCHB + MAINB)        /* 400 */

__device__ float g_partial[GRID][5]; // fully rewritten each run — replay safe
__device__ int   g_done;             // reset to 0 by last block each run

__device__ __forceinline__ float clogf_(float v){ return fmaxf(__logf(v), -100.0f); }
__device__ __forceinline__ float sigf_(float v){ return __fdividef(1.0f, 1.0f + __expf(-v)); }

// CIoU argmax over 9 anchors at L0 scale (scale-invariant across levels)
__device__ __forceinline__ int ciou_argmax(float tw, float th){
  float at_t = atanf(tw/th);
  float twth = tw*th;
  float best = -3.0e38f; int bi = 0;
  #pragma unroll
  for (int k = 0; k < 9; k++){
    float wb = cANW[k]*0.125f, hb = cANH[k]*0.125f;
    float ai = fminf(tw,wb)*fminf(th,hb);
    float au = twth + wb*hb - ai;
    float iou = ai/au;
    float mw = fmaxf(tw,wb), mh = fmaxf(th,hb);
    float c2 = mw*mw + mh*mh + 1e-16f;
    float dw = tw-wb, dh = th-hb;
    float rho2 = (dw*dw + dh*dh)*0.25f;
    float da = at_t - cATAN[k];
    float v = 0.40528473455296503f*(da*da);      // 4/pi^2
    float alpha = v/(1.0f - iou + v);
    float ciou = iou - (rho2/c2 + v*alpha);
    if (ciou > best){ best = ciou; bi = k; }     // first-max == jnp.argmax
  }
  return bi;
}

// ------------------------------------------------------------------ main-path context (corner form, 4 cells/thread)
template<int L, int FS>
struct Ctx {
  float so[4], plx[4], ply[4], phx[4], phy[4], ap3[4];
  int base;
};

template<int L, int FS>
__device__ __forceinline__ void main_pre(const float* __restrict__ x, int b, int chunk, Ctx<L,FS>& c){
  constexpr int FSQ = FS*FS;
  constexpr float invs = (L==0) ? 0.125f : 0.0625f;
  c.base = chunk*CELLS + (int)threadIdx.x*4;
  #pragma unroll
  for (int k = 0; k < 4; k++){
    c.so[k] = 0.f; c.plx[k] = 3e4f; c.phx[k] = 3e4f; c.ply[k] = 0.f; c.phy[k] = 0.f; c.ap3[k] = 1.f;
  }
  if (c.base < 3*FSQ){
    int a = c.base/FSQ, cell = c.base - a*FSQ;
    int j0 = cell / FS, i0 = cell - j0*FS;       // FS%4==0 => 4 cells share a row
    const float* xp = x + (b*255 + a*85)*FSQ + cell;
    float4 O0 = __ldg((const float4*)(xp));
    float4 O1 = __ldg((const float4*)(xp+FSQ));
    float4 O2 = __ldg((const float4*)(xp+2*FSQ));
    float4 O3 = __ldg((const float4*)(xp+3*FSQ));
    float4 O4 = __ldg((const float4*)(xp+4*FSQ));
    float AW = cANW[3*L+a]*invs, AH = cANH[3*L+a]*invs;
    float o0a[4] = {O0.x,O0.y,O0.z,O0.w};
    float o1a[4] = {O1.x,O1.y,O1.z,O1.w};
    float o2a[4] = {O2.x,O2.y,O2.z,O2.w};
    float o3a[4] = {O3.x,O3.y,O3.z,O3.w};
    float o4a[4] = {O4.x,O4.y,O4.z,O4.w};
    float fj = (float)j0;
    #pragma unroll
    for (int k = 0; k < 4; k++){
      c.so[k] = sigf_(o4a[k]);
      float pw = __expf(o2a[k])*AW, ph = __expf(o3a[k])*AH;
      float px = (float)(i0+k) + sigf_(o0a[k]);
      float py = fj + sigf_(o1a[k]);
      float hw = 0.5f*pw, hh = 0.5f*ph;
      c.plx[k] = px-hw; c.phx[k] = px+hw; c.ply[k] = py-hh; c.phy[k] = py+hh;
      c.ap3[k] = pw*ph*(1.0f/3.0f);
    }
  }
}

template<int L, int FS>
__device__ __forceinline__ void main_post(const Ctx<L,FS>& c, int nv, int hm,
    const float4* __restrict__ s_box, const float* __restrict__ s_ar3,
    const unsigned char* __restrict__ s_mbit, float* acc){
  constexpr int FSQ = FS*FS;
  bool un[4] = {false,false,false,false};
  if (c.base < 3*FSQ){
    uchar4 mb = *(const uchar4*)(s_mbit + threadIdx.x*4);  // in-chunk offset = tid*4
    unsigned char m[4] = {mb.x, mb.y, mb.z, mb.w};
    #pragma unroll
    for (int k = 0; k < 4; k++){
      if (m[k]){ acc[2] += -clogf_(c.so[k]); float e = c.so[k]-1.f; acc[4] += e*e; }
      else un[k] = true;
    }
  }
  float vmax[4] = {-1e30f,-1e30f,-1e30f,-1e30f};
  if (hm){
    #pragma unroll 4
    for (int t = 0; t < nv; t++){
      float4 tb = s_box[t];
      float ar3 = s_ar3[t];
      #pragma unroll
      for (int k = 0; k < 4; k++){
        float wi = fmaxf(fminf(c.phx[k], tb.z) - fmaxf(c.plx[k], tb.x), 0.f);
        float hi = fminf(c.phy[k], tb.w) - fmaxf(c.ply[k], tb.y);
        vmax[k] = fmaxf(vmax[k], fmaf(wi, hi, -ar3));   // iou>.5 <=> ai-at/3 > ap/3
      }
    }
  }
  #pragma unroll
  for (int k = 0; k < 4; k++){
    if (un[k] && !(vmax[k] > c.ap3[k])){ acc[2] += -clogf_(1.f - c.so[k]); acc[4] += c.so[k]*c.so[k]; }
  }
}

// scalar variant for L2 (FSQ=361, not divisible by 4)
struct Ctx2 {
  float so[4], plx[4], ply[4], phx[4], phy[4], ap3[4];
  int base;
};

__device__ __forceinline__ void main_pre2(const float* __restrict__ x, int b, int chunk, Ctx2& c){
  constexpr int FSQ = FSQ2;
  constexpr float invs = 0.03125f;
  c.base = chunk*CELLS + (int)threadIdx.x;
  #pragma unroll
  for (int k = 0; k < 4; k++){
    int cc = c.base + k*TPB;
    c.so[k] = 0.f; c.plx[k] = 3e4f; c.phx[k] = 3e4f; c.ply[k] = 0.f; c.phy[k] = 0.f; c.ap3[k] = 1.f;
    if (cc < 3*FSQ){
      int a = cc/FSQ, cell = cc - a*FSQ;
      const float* xp = x + (b*255 + a*85)*FSQ + cell;
      c.so[k] = sigf_(__ldg(xp + 4*FSQ));
      float AW = cANW[6+a]*invs, AH = cANH[6+a]*invs;
      float pw = __expf(__ldg(xp+2*FSQ))*AW, ph = __expf(__ldg(xp+3*FSQ))*AH;
      float px = (float)(cell % 19) + sigf_(__ldg(xp));
      float py = (float)(cell / 19) + sigf_(__ldg(xp+FSQ));
      float hw = 0.5f*pw, hh = 0.5f*ph;
      c.plx[k] = px-hw; c.phx[k] = px+hw; c.ply[k] = py-hh; c.phy[k] = py+hh;
      c.ap3[k] = pw*ph*(1.0f/3.0f);
    }
  }
}

__device__ __forceinline__ void main_post2(const Ctx2& c, int nv, int hm,
    const float4* __restrict__ s_box, const float* __restrict__ s_ar3,
    const unsigned char* __restrict__ s_mbit, float* acc){
  constexpr int FSQ = FSQ2;
  bool un[4] = {false,false,false,false};
  #pragma unroll
  for (int k = 0; k < 4; k++){
    int cc = c.base + k*TPB;
    if (cc < 3*FSQ){
      if (s_mbit[(int)threadIdx.x + k*TPB]){ acc[2] += -clogf_(c.so[k]); float e = c.so[k]-1.f; acc[4] += e*e; }
      else un[k] = true;
    }
  }
  float vmax[4] = {-1e30f,-1e30f,-1e30f,-1e30f};
  if (hm){
    #pragma unroll 4
    for (int t = 0; t < nv; t++){
      float4 tb = s_box[t];
      float ar3 = s_ar3[t];
      #pragma unroll
      for (int k = 0; k < 4; k++){
        float wi = fmaxf(fminf(c.phx[k], tb.z) - fmaxf(c.plx[k], tb.x), 0.f);
        float hi = fminf(c.phy[k], tb.w) - fmaxf(c.ply[k], tb.y);
        vmax[k] = fmaxf(vmax[k], fmaf(wi, hi, -ar3));
      }
    }
  }
  #pragma unroll
  for (int k = 0; k < 4; k++){
    if (un[k] && !(vmax[k] > c.ap3[k])){ acc[2] += -clogf_(1.f - c.so[k]); acc[4] += c.so[k]*c.so[k]; }
  }
}

// ------------------------------------------------------------------ THE kernel: fully block-local, one launch
__global__ __launch_bounds__(TPB) void k_all(
    const float* __restrict__ x0, const float* __restrict__ x1, const float* __restrict__ x2,
    const float* __restrict__ labels, float* __restrict__ gout)
{
  __shared__ float4 s_box[NT];
  __shared__ float  s_ar3[NT];
  __shared__ float4 s_cbox[NT];        // y-culled truths for this block
  __shared__ float  s_car3[NT];
  __shared__ int    s_cnv;
  __shared__ __align__(4) unsigned char s_mbit[CELLS];
  __shared__ float  s_lab[NT][5];
  __shared__ int    s_key[NT];
  __shared__ int    s_win[NT];
  __shared__ float  s_red[5];
  __shared__ int    s_cnt;
  __shared__ int    s_last;

  int bid = blockIdx.x, tid = threadIdx.x;
  if (tid < 5) s_red[tid] = 0.f;
  float acc[5] = {0.f,0.f,0.f,0.f,0.f};

  if (bid < MATCHB){
    // ================= MATCH BLOCK (one per b): self-contained =================
    int b = bid;
    int key = -1;
    if (tid < NT){
      const float* lp = labels + (b*NT + tid)*5;
      float a0 = lp[0], a1 = lp[1], a2 = lp[2], a3 = lp[3], a4 = lp[4];
      s_lab[tid][0]=a0; s_lab[tid][1]=a1; s_lab[tid][2]=a2; s_lab[tid][3]=a3; s_lab[tid][4]=a4;
      bool valid = (a0+a1+a2+a3+a4) > 0.0f;
      if (valid){
        int bi = ciou_argmax((a2-a0)*0.125f, (a3-a1)*0.125f);
        int Lm = bi/3;
        const float invsA[3] = {0.125f, 0.0625f, 0.03125f};
        const int   fsA[3]   = {76, 38, 19};
        float invs = invsA[Lm]; int fs = fsA[Lm];
        float tx = (a2+a0)*(0.5f*invs), ty = (a3+a1)*(0.5f*invs);
        int ii = (int)tx; ii = ii < 0 ? 0 : (ii > fs-1 ? fs-1 : ii);
        int jj = (int)ty; jj = jj < 0 ? 0 : (jj > fs-1 ? fs-1 : jj);
        int cc = (bi - 3*Lm)*fs*fs + jj*fs + ii;      // < 17328 < 2^16
        key = (Lm << 16) | cc;
      }
      s_key[tid] = key;
    }
    __syncthreads();
    if (tid < NT){
      int w = 0;
      if (key >= 0){                                   // winner = last t with this (level,cell)
        w = 1;
        for (int t2 = tid+1; t2 < NT; t2++) if (s_key[t2] == key){ w = 0; break; }
      }
      s_win[tid] = w;
    }
    __syncthreads();
    int wrp = tid >> 5, lane = tid & 31;
    for (int t = wrp; t < NT; t += 8){                 // warp-uniform entry selection
      if (!s_win[t]) continue;
      int k2 = s_key[t];
      int Lm = k2 >> 16, cc = k2 & 0xFFFF;
      const int   fsqA[3]  = {FSQ0, FSQ1, FSQ2};
      const float invsA[3] = {0.125f, 0.0625f, 0.03125f};
      const float* x = (Lm==0) ? x0 : ((Lm==1) ? x1 : x2);
      int FSQ = fsqA[Lm];
      float invs = invsA[Lm];
      int a = cc/FSQ, cell = cc - a*FSQ;
      const float* xp = x + (b*255 + a*85)*FSQ + cell;
      float a0 = s_lab[t][0], a1 = s_lab[t][1], a2 = s_lab[t][2], a3 = s_lab[t][3], a4 = s_lab[t][4];
      float tx = (a2+a0)*(0.5f*invs), ty = (a3+a1)*(0.5f*invs);
      float tw = (a2-a0)*invs,        th = (a3-a1)*invs;
      float scl = sqrtf(2.0f - tw*th/(float)FSQ);
      int cl = (int)a4;
      for (int c = lane; c < NCLS; c += 32){
        float s = sigf_(__ldg(xp + (5+c)*FSQ));
        if (c == cl){ acc[3] += -clogf_(s);       float er = s-1.f; acc[4] += er*er; }
        else        { acc[3] += -clogf_(1.f - s); acc[4] += s*s; }
      }
      if (lane == 0){
        float AW = cANW[3*Lm+a]*invs, AH = cANH[3*Lm+a]*invs;
        float o0 = __ldg(xp), o1 = __ldg(xp+FSQ), o2 = __ldg(xp+2*FSQ), o3 = __ldg(xp+3*FSQ);
        float s0 = sigf_(o0), s1 = sigf_(o1);
        float fx = tx - truncf(tx), fy = ty - truncf(ty);
        float lw = __logf(tw/AW + 1e-16f), lh = __logf(th/AH + 1e-16f);
        float w2 = scl*scl;
        acc[0] += w2*( -(fx*clogf_(s0) + (1.f-fx)*clogf_(1.f-s0))
                       -(fy*clogf_(s1) + (1.f-fy)*clogf_(1.f-s1)) );
        float dx = (o2-lw)*scl, dy = (o3-lh)*scl;
        acc[1] += 0.5f*(dx*dx + dy*dy);
        float e0 = s0-fx, e1 = s1-fy;
        acc[4] += e0*e0 + e1*e1 + dx*dx + dy*dy;
      }
    }
  } else {
    // ================= MAIN BLOCK: self-contained prep + obj loss =================
    int mbid = bid - MATCHB;
    int Lv, b, chunk;
    if (mbid < NB*CH0)            { Lv = 0; b = mbid % NB;                    chunk = mbid / NB; }
    else if (mbid < NB*(CH0+CH1)) { int r = mbid - NB*CH0;       Lv = 1; b = r % NB; chunk = r / NB; }
    else                          { int r = mbid - NB*(CH0+CH1); Lv = 2; b = r % NB; chunk = r / NB; }

    // block's pred-center row window [rowlo, rowhi+1]
    int FSv  = (Lv==0) ? 76 : ((Lv==1) ? 38 : 19);
    int FSQv = FSv*FSv;
    int rowlo, rowhi;
    {
      int beg = chunk*CELLS;
      int end = min(beg + CELLS - 1, 3*FSQv - 1);
      if (Lv == 2 || (beg/FSQv) != (end/FSQv)){ rowlo = 0; rowhi = FSv-1; }   // spans planes (or strided L2)
      else { rowlo = (beg % FSQv)/FSv; rowhi = (end % FSQv)/FSv; }
    }

    // phase A: in-block truth prep (bitmap zero + boxes + argmax)
    ((int*)s_mbit)[tid] = 0;                           // 256 ints = 1024 B
    if (tid == 0) s_cnt = 0;
    int mi = -1;
    if (tid < NT){
      const float* lp = labels + (b*NT + tid)*5;
      float a0 = lp[0], a1 = lp[1], a2 = lp[2], a3 = lp[3], a4 = lp[4];
      bool valid = (a0+a1+a2+a3+a4) > 0.0f;
      if (valid){
        int bi = ciou_argmax((a2-a0)*0.125f, (a3-a1)*0.125f);
        float invs = (Lv==0) ? 0.125f : ((Lv==1) ? 0.0625f : 0.03125f);
        int   fs   = FSv;
        float tx = (a2+a0)*(0.5f*invs), ty = (a3+a1)*(0.5f*invs);
        float tw = (a2-a0)*invs,        th = (a3-a1)*invs;
        int p = atomicAdd(&s_cnt, 1);                  // order-free: feeds exact max only
        s_box[p] = make_float4(tx - tw*0.5f, ty - th*0.5f, tx + tw*0.5f, ty + th*0.5f);
        s_ar3[p] = tw*th*(1.0f/3.0f);
        if (bi/3 == Lv){
          int ii = (int)tx; ii = ii < 0 ? 0 : (ii > fs-1 ? fs-1 : ii);
          int jj = (int)ty; jj = jj < 0 ? 0 : (jj > fs-1 ? fs-1 : jj);
          mi = (bi - 3*Lv)*fs*fs + jj*fs + ii;
        }
      }
    }
    int hm = __syncthreads_or(mi >= 0);                // also fences s_box/s_cnt/bitmap-zero
    if (mi >= 0){
      int off = mi - chunk*CELLS;
      if (off >= 0 && off < CELLS) s_mbit[off] = 1;    // boolean suffices for obj path
    }
    // warp 0: exact y-window cull (ignore fires only if pred center within 7/6*ht of truth; use 1.2)
    if (tid < 32){
      int nvAll = s_cnt;
      unsigned lt = (1u << tid) - 1u;
      int n2 = 0;
      float flo = (float)rowlo, fhi = (float)(rowhi + 1);
      #pragma unroll
      for (int r = 0; r < 2; r++){
        int t = tid + r*32;
        bool keep = false; float4 tb; float ar = 0.f;
        if (t < nvAll){
          tb = s_box[t]; ar = s_ar3[t];
          float ht = tb.w - tb.y;
          keep = (tb.w + 1.2f*ht > flo) && (tb.y - 1.2f*ht < fhi);
        }
        unsigned m = __ballot_sync(~0u, keep);
        if (keep){ int p = n2 + __popc(m & lt); s_cbox[p] = tb; s_car3[p] = ar; }
        n2 += __popc(m);
      }
      if (tid == 0) s_cnv = n2;
    }

    // phase B: channel loads + pred boxes (no smem), sync (covers bitmap + cull), ignore loop
    if (Lv == 0){
      Ctx<0,76> c; main_pre<0,76>(x0, b, chunk, c);
      __syncthreads();
      main_post<0,76>(c, s_cnv, hm, s_cbox, s_car3, s_mbit, acc);
    } else if (Lv == 1){
      Ctx<1,38> c; main_pre<1,38>(x1, b, chunk, c);
      __syncthreads();
      main_post<1,38>(c, s_cnv, hm, s_cbox, s_car3, s_mbit, acc);
    } else {
      Ctx2 c; main_pre2(x2, b, chunk, c);
      __syncthreads();
      main_post2(c, s_cnv, hm, s_cbox, s_car3, s_mbit, acc);
    }
  }

  // ================= block reduction -> per-block partial =================
  #pragma unroll
  for (int k = 0; k < 5; k++){
    float v = acc[k];
    #pragma unroll
    for (int off = 16; off > 0; off >>= 1) v += __shfl_down_sync(0xffffffffu, v, off);
    if ((tid & 31) == 0 && v != 0.f) atomicAdd(&s_red[k], v);
  }
  __syncthreads();
  if (tid < 5){ g_partial[bid][tid] = s_red[tid]; __threadfence(); }
  __syncthreads();
  if (tid == 0) s_last = (atomicAdd(&g_done, 1) == GRID-1);
  __syncthreads();

  // ================= last block: final sum, writes all of gout =================
  if (s_last){
    int wrp = tid >> 5, lane = tid & 31;
    if (wrp < 5){
      float v = 0.f;
      for (int r = lane; r < GRID; r += 32) v += __ldcg(&g_partial[r][wrp]);
      #pragma unroll
      for (int off = 16; off > 0; off >>= 1) v += __shfl_down_sync(0xffffffffu, v, off);
      if (lane == 0) s_red[wrp] = v;
    }
    __syncthreads();
    if (tid == 0){
      g_done = 0;                                      // restore invariant for next replay
      float lxy = s_red[0], lwh = s_red[1], lobj = s_red[2], lcls = s_red[3], ll2 = s_red[4];
      gout[0] = lxy + lwh + lobj + lcls;
      gout[1] = lxy; gout[2] = lwh; gout[3] = lobj; gout[4] = lcls; gout[5] = ll2;
    }
  }
}

// ------------------------------------------------------------------ launch: ONE node
extern "C" void kernel_launch(void* const* d_in, const int* in_sizes, int n_in,
                              void* d_out, int out_size)
{
  const float* x0     = (const float*)d_in[0];
  const float* x1     = (const float*)d_in[1];
  const float* x2     = (const float*)d_in[2];
  const float* labels = (const float*)d_in[3];
  float* gout = (float*)d_out;
  (void)in_sizes; (void)n_in; (void)out_size;

  k_all<<<GRID, TPB>>>(x0, x1, x2, labels, gout);
}